// round 16
// baseline (speedup 1.0000x reference)
#include <cuda_runtime.h>
#include <cuda_fp16.h>
#include <cstdint>
#include <cstddef>
#include <cmath>

// Problem constants
#define T_STEPS 1000
#define BATCH   64
#define NDIM    512
#define KDIM    512
#define MROWS   (BATCH * T_STEPS)   // 64000

#define NT_CHUNKS 4
#define T_CHK     (T_STEPS / NT_CHUNKS)        // 250 t-steps per chunk
#define ROWS_CHK  (T_CHK * BATCH)              // 16000 m-rows per chunk

static constexpr size_t PLANE      = (size_t)BATCH * NDIM;          // 32768
static constexpr size_t STATES_OFF = (size_t)T_STEPS * PLANE;       // outputs plane elems
static constexpr size_t DEC_OFF    = STATES_OFF + 3 * STATES_OFF;   // after states [T,3,B,N]

// Scratch. g_I is [t, b, n]-major: row m = t*BATCH + b.
__device__ __align__(16) float g_I[(size_t)MROWS * NDIM];
__device__ float g_r[T_STEPS * BATCH];
__device__ float g_u[PLANE];     // carried scan state between t-chunks
__device__ float g_v[PLANE];

// ---------------------------------------------------------------------------
// fp16 Dekker-pair: x -> half2(hi=rn16(x), lo=rn16(x-hi)), interleaved along
// mma-k. pass1 (A x B) = hi*hi + lo*lo; pass2 (swap16(A) x B) = hi*lo + lo*hi.
// Sum = full (hi+lo)(hi+lo) product, ~2^-22 relative error.
// ---------------------------------------------------------------------------
__device__ __forceinline__ uint32_t pack_hilo(float x) {
    __half h = __float2half_rn(x);
    float r = x - __half2float(h);
    __half2 p = __halves2half2(h, __float2half_rn(r));
    return *reinterpret_cast<uint32_t*>(&p);
}

__device__ __forceinline__ void mma_f16(float* c, const uint32_t* a, const uint32_t* b) {
    asm volatile(
        "mma.sync.aligned.m16n8k16.row.col.f32.f16.f16.f32 "
        "{%0,%1,%2,%3}, {%4,%5,%6,%7}, {%8,%9}, {%0,%1,%2,%3};\n"
        : "+f"(c[0]), "+f"(c[1]), "+f"(c[2]), "+f"(c[3])
        : "r"(a[0]), "r"(a[1]), "r"(a[2]), "r"(a[3]), "r"(b[0]), "r"(b[1]));
}

__device__ __forceinline__ void ldsm_x4(uint32_t* r, uint32_t saddr) {
    asm volatile("ldmatrix.sync.aligned.m8n8.x4.shared.b16 {%0,%1,%2,%3}, [%4];"
                 : "=r"(r[0]), "=r"(r[1]), "=r"(r[2]), "=r"(r[3]) : "r"(saddr));
}

// ---------------------------------------------------------------------------
// Kernel 1: I[m,:] = X[perm(m),:] @ W1^T.
// R16: CTA tile 64x128 (halved M) to cut wave quantization: 1000 CTAs/chunk
// over 148 SMs = 6.76 -> 7 waves (3.6% waste) vs 500 CTAs -> 3.38 -> 4 (18%).
// 512 threads, 16 warps 4(M,m16) x 4(N,n32), warp tile 16x32, ldmatrix loads,
// register-staged double buffer, stride-36-word smem (54KB used).
// 1 CTA/SM FORCED via 120KB dynamic smem request (2x120 > 228KB limit).
// ---------------------------------------------------------------------------
#define BKR    32
#define GCHUNK (KDIM / BKR)        // 16
#define WSTR   36
#define TILE_A (64 * WSTR)         // 2304 words
#define TILE_B (128 * WSTR)        // 4608 words
#define STAGEW (TILE_A + TILE_B)   // 6912 words = 27648 B
#define SMEM_FORCE_BYTES 122880    // force 1 CTA/SM (2x would exceed 228KB)

struct LdgRegs { float4 a; float4 b[2]; };   // 4 A floats + 8 B floats

__device__ __forceinline__ void ldg_chunk(LdgRegs& r, const float* __restrict__ xptr,
                                          const float* __restrict__ wptr, int ck)
{
    r.a = *(const float4*)(xptr + ck * BKR);
    const float4* wa = (const float4*)(wptr + ck * BKR);
    r.b[0] = wa[0]; r.b[1] = wa[1];
}

// A loader: row = tid>>3 (0..63), 4-word quarter (tid&7)*4.
// B loader: row = tid>>2 (0..127), 8-word half (tid&3)*8.
__device__ __forceinline__ void sts_chunk(uint32_t* stage, const LdgRegs& r, int tid)
{
    const int arow = tid >> 3, akb = (tid & 7) * 4;
    const int brow = tid >> 2, bkb = (tid & 3) * 8;
    uint32_t* sA = stage + arow * WSTR + akb;
    uint32_t* sB = stage + TILE_A + brow * WSTR + bkb;
    uint4 wa;
    wa.x = pack_hilo(r.a.x); wa.y = pack_hilo(r.a.y);
    wa.z = pack_hilo(r.a.z); wa.w = pack_hilo(r.a.w);
    *(uint4*)sA = wa;
    const float* fb = (const float*)r.b;
    #pragma unroll
    for (int j = 0; j < 2; j++) {
        uint4 w;
        w.x = pack_hilo(fb[j * 4 + 0]); w.y = pack_hilo(fb[j * 4 + 1]);
        w.z = pack_hilo(fb[j * 4 + 2]); w.w = pack_hilo(fb[j * 4 + 3]);
        ((uint4*)sB)[j] = w;
    }
}

__device__ __forceinline__ void compute_chunk(uint32_t stage_saddr,
                                              float (&acc)[4][4],
                                              uint32_t aOff, uint32_t bOff)
{
    #pragma unroll
    for (int s = 0; s < 4; s++) {
        const uint32_t kByte = (uint32_t)(s * 8) * 4u;
        uint32_t A[4];
        ldsm_x4(A, stage_saddr + aOff + kByte);                                 // m16k16
        uint32_t Bt[2][4];
        ldsm_x4(Bt[0], stage_saddr + bOff + kByte);                             // nt 0,1
        ldsm_x4(Bt[1], stage_saddr + bOff + (uint32_t)(16 * WSTR * 4) + kByte); // nt 2,3

        // pass 1: hi*hi + lo*lo — distinct accumulators
        #pragma unroll
        for (int nt = 0; nt < 4; nt++)
            mma_f16(acc[nt], A, &Bt[nt >> 1][(nt & 1) * 2]);
        // pass 2: hi*lo + lo*hi — swap A halves in place (A reloaded next slice)
        #pragma unroll
        for (int j = 0; j < 4; j++)
            A[j] = __byte_perm(A[j], 0, 0x1032);
        #pragma unroll
        for (int nt = 0; nt < 4; nt++)
            mma_f16(acc[nt], A, &Bt[nt >> 1][(nt & 1) * 2]);
    }
}

__global__ __launch_bounds__(512, 1) void gemm_f16pair_kernel(const float* __restrict__ X,
                                                              const float* __restrict__ W,
                                                              int bm_base)
{
    extern __shared__ uint32_t smemw[];      // uses 2 stages * 6912 words = 54KB
    const int tid  = threadIdx.x;
    const int wid  = tid >> 5;
    const int lane = tid & 31;
    const int wm   = wid & 3;                // 0..3 (M, 16 rows each)
    const int wn   = wid >> 2;               // 0..3 (N, 32 cols each)
    const int bn   = blockIdx.x * 128;       // n fastest: 4 CTAs share X tile -> L2
    const int bm   = bm_base + blockIdx.y * 64;

    const uint32_t smem_saddr = (uint32_t)__cvta_generic_to_shared(smemw);

    // ldmatrix per-lane offsets (stage-relative, bytes) — R9-proven formulas.
    const int lm = lane & 7;
    // A x4 (m16k16): M0=row+0/w0, M1=row+8/w0, M2=row+0/w4, M3=row+8/w4
    const int aRow = wm * 16 + lm + ((lane >> 3) & 1) * 8;
    const int aWrd = ((lane >> 4) & 1) * 4;
    const uint32_t aOff = (uint32_t)(aRow * WSTR + aWrd) * 4u;
    // B x4: M0=row+0/w0, M1=row+0/w4, M2=row+8/w0, M3=row+8/w4
    const int bRow = wn * 32 + lm + ((lane >> 4) & 1) * 8;
    const int bWrd = ((lane >> 3) & 1) * 4;
    const uint32_t bOff = (uint32_t)(TILE_A + bRow * WSTR + bWrd) * 4u;

    // loader pointers; X row = b*T_STEPS + t for m = t*BATCH + b
    const int amrow = bm + (tid >> 3);
    const int xrow  = (amrow & (BATCH - 1)) * T_STEPS + (amrow / BATCH);
    const float* xptr = X + (size_t)xrow * KDIM + (tid & 7) * 4;
    const float* wptr = W + (size_t)(bn + (tid >> 2)) * KDIM + (tid & 3) * 8;

    float acc[4][4];
    #pragma unroll
    for (int nt = 0; nt < 4; nt++)
        #pragma unroll
        for (int j = 0; j < 4; j++) acc[nt][j] = 0.f;

    {
        LdgRegs r0;
        ldg_chunk(r0, xptr, wptr, 0);
        sts_chunk(smemw, r0, tid);
    }
    __syncthreads();

    #pragma unroll 1
    for (int ck = 0; ck < GCHUNK; ck++) {
        const int cur = ck & 1;
        LdgRegs nr;
        if (ck < GCHUNK - 1) ldg_chunk(nr, xptr, wptr, ck + 1);   // LDGs in flight
        compute_chunk(smem_saddr + (uint32_t)(cur * STAGEW) * 4u, acc, aOff, bOff);
        if (ck < GCHUNK - 1) sts_chunk(smemw + (cur ^ 1) * STAGEW, nr, tid);
        __syncthreads();
    }

    // Epilogue: direct float2 stores to g_I
    {
        const int r0 = bm + wm * 16 + (lane >> 2);
        #pragma unroll
        for (int nt = 0; nt < 4; nt++) {
            const int c = bn + wn * 32 + nt * 8 + 2 * (lane & 3);
            *(float2*)(g_I + (size_t)r0 * NDIM + c)       = make_float2(acc[nt][0], acc[nt][1]);
            *(float2*)(g_I + (size_t)(r0 + 8) * NDIM + c) = make_float2(acc[nt][2], acc[nt][3]);
        }
    }
}

// ---------------------------------------------------------------------------
// Kernel 2: Izhikevich scan over one t-chunk [tbase, tbase+T_CHK).
// I is [t,b,n]: thread g reads g_I[t*PLANE + g] — fully coalesced per warp.
// (u,v) carried via g_u/g_v between chunks (chunk 0 reads state_snn).
// ---------------------------------------------------------------------------
struct NeuronP { float TS, V2, V1, V0, KA, Bp, TH, Cc, D; };

__device__ __forceinline__ void snn_step(float Ic, int t, int g,
                                         const NeuronP& P, float& u, float& v,
                                         float* __restrict__ out)
{
    float t0 = P.V0 - u + Ic;
    t0 = fmaf(P.V1, v, t0);
    t0 = fmaf(P.V2, v * v, t0);
    const float vn = fmaf(P.TS, t0, v);
    const float un = fmaf(P.KA, fmaf(P.Bp, v, -u), u);
    const bool  sp = (vn - P.TH) > 0.f;
    const float s  = sp ? 1.f : 0.f;
    const float vo = sp ? P.Cc : vn;
    const float uo = sp ? (un + P.D) : un;

    out[(size_t)t * PLANE + g] = s;
    const size_t sb = STATES_OFF + (size_t)t * (3 * PLANE) + g;
    out[sb]             = uo;
    out[sb + PLANE]     = vo;
    out[sb + 2 * PLANE] = s;
    u = uo; v = vo;
}

__global__ __launch_bounds__(128) void scan_kernel(
    const float* __restrict__ st,
    const float* __restrict__ pa,  const float* __restrict__ pb,
    const float* __restrict__ pc,  const float* __restrict__ pd,
    const float* __restrict__ pv2, const float* __restrict__ pv1,
    const float* __restrict__ pv0, const float* __restrict__ ptau,
    const float* __restrict__ pth, const float* __restrict__ pts,
    float* __restrict__ out, int tbase)
{
    const int g = blockIdx.x * 128 + threadIdx.x;
    const int n = g & (NDIM - 1);

    NeuronP P;
    P.TS = pts[n];
    P.V2 = pv2[n]; P.V1 = pv1[n]; P.V0 = pv0[n];
    P.KA = P.TS / ptau[n] * pa[n];
    P.Bp = pb[n]; P.TH = pth[n]; P.Cc = pc[n]; P.D = pd[n];

    float u, v;
    if (tbase == 0) { u = st[g]; v = st[PLANE + g]; }
    else            { u = g_u[g]; v = g_v[g]; }

    const float* Ip = g_I + (size_t)tbase * PLANE + g;   // step stride = PLANE

    float bufA[8], bufB[8];
    #pragma unroll
    for (int p = 0; p < 8; p++) bufA[p] = __ldcs(Ip + (size_t)p * PLANE);

    // Main loop: after it, bufA holds steps t0..t0+7 with Ip at base+t0*PLANE.
    int t0 = 0;
    #pragma unroll 1
    for (; t0 + 24 <= T_CHK; t0 += 16) {
        #pragma unroll
        for (int p = 0; p < 8; p++) bufB[p] = __ldcs(Ip + (size_t)(8 + p) * PLANE);
        #pragma unroll
        for (int p = 0; p < 8; p++) snn_step(bufA[p], tbase + t0 + p, g, P, u, v, out);
        #pragma unroll
        for (int p = 0; p < 8; p++) bufA[p] = __ldcs(Ip + (size_t)(16 + p) * PLANE);
        #pragma unroll
        for (int p = 0; p < 8; p++) snn_step(bufB[p], tbase + t0 + 8 + p, g, P, u, v, out);
        Ip += 16 * PLANE;
    }
    // Tail: 8 from bufA, then direct loads for remaining steps.
    #pragma unroll
    for (int p = 0; p < 8; p++) snn_step(bufA[p], tbase + t0 + p, g, P, u, v, out);
    #pragma unroll 1
    for (int p = 8; t0 + p < T_CHK; p++)
        snn_step(__ldcs(Ip + (size_t)p * PLANE), tbase + t0 + p, g, P, u, v, out);

    g_u[g] = u;
    g_v[g] = v;
}

// ---------------------------------------------------------------------------
// Kernel 3: r[t*B+b] = sum_n s[t,b,n]*W2[n], chunked by t (tb_base offset)
// ---------------------------------------------------------------------------
__global__ __launch_bounds__(128) void readout_reduce_kernel(
    const float* __restrict__ out, const float* __restrict__ W2, int tb_base)
{
    const int tb = tb_base + blockIdx.x;
    const float* sp = out + (size_t)tb * NDIM;
    const int tid = threadIdx.x;

    float sum = 0.f;
    #pragma unroll
    for (int j = 0; j < 4; j++) {
        const int n = tid + j * 128;
        sum = fmaf(sp[n], W2[n], sum);
    }
    #pragma unroll
    for (int o = 16; o > 0; o >>= 1)
        sum += __shfl_xor_sync(0xffffffffu, sum, o);

    __shared__ float ws[4];
    if ((tid & 31) == 0) ws[tid >> 5] = sum;
    __syncthreads();
    if (tid == 0) g_r[tb] = (ws[0] + ws[1]) + (ws[2] + ws[3]);
}

// ---------------------------------------------------------------------------
// Kernel 4: li recurrence — warp-parallel linear-recurrence scan (frozen)
// ---------------------------------------------------------------------------
__global__ void li_kernel(const float* __restrict__ stLI,
                          const float* __restrict__ leak,
                          float* __restrict__ out)
{
    const int b = blockIdx.x;
    const int lane = threadIdx.x;
    const float lk = leak[0];
    const float l1 = lk, l2 = l1 * l1, l4 = l2 * l2, l8 = l4 * l4, l16 = l8 * l8;
    float lpow = lk;
    {
        float sq[5] = {l1, l2, l4, l8, l16};
        #pragma unroll
        for (int i = 0; i < 5; i++)
            if ((lane >> i) & 1) lpow *= sq[i];
    }

    float carry = stLI[b];
    float x = g_r[lane * BATCH + b];

    #pragma unroll 1
    for (int t0 = 0; t0 < T_STEPS; t0 += 32) {
        const int tn = t0 + 32 + lane;
        const float xn = (tn < T_STEPS) ? g_r[tn * BATCH + b] : 0.f;

        float y = x, up;
        up = __shfl_up_sync(0xffffffffu, y, 1);  if (lane >= 1)  y = fmaf(l1,  up, y);
        up = __shfl_up_sync(0xffffffffu, y, 2);  if (lane >= 2)  y = fmaf(l2,  up, y);
        up = __shfl_up_sync(0xffffffffu, y, 4);  if (lane >= 4)  y = fmaf(l4,  up, y);
        up = __shfl_up_sync(0xffffffffu, y, 8);  if (lane >= 8)  y = fmaf(l8,  up, y);
        up = __shfl_up_sync(0xffffffffu, y, 16); if (lane >= 16) y = fmaf(l16, up, y);

        const float li = fmaf(lpow, carry, y);
        if (t0 + lane < T_STEPS)
            out[DEC_OFF + (size_t)(t0 + lane) * BATCH + b] = li;
        carry = __shfl_sync(0xffffffffu, li, 31);
        x = xn;
    }
}

// ---------------------------------------------------------------------------
extern "C" void kernel_launch(void* const* d_in, const int* in_sizes, int n_in,
                              void* d_out, int out_size)
{
    const float* x    = (const float*)d_in[0];
    const float* st   = (const float*)d_in[1];
    const float* stLI = (const float*)d_in[2];
    const float* W1   = (const float*)d_in[3];
    const float* W2   = (const float*)d_in[4];
    const float* a_   = (const float*)d_in[5];
    const float* b_   = (const float*)d_in[6];
    const float* c_   = (const float*)d_in[7];
    const float* d_   = (const float*)d_in[8];
    const float* v2_  = (const float*)d_in[9];
    const float* v1_  = (const float*)d_in[10];
    const float* v0_  = (const float*)d_in[11];
    const float* tau_ = (const float*)d_in[12];
    const float* th_  = (const float*)d_in[13];
    const float* lk_  = (const float*)d_in[14];
    const float* ts_  = (const float*)d_in[15];
    float* out = (float*)d_out;

    // One-time side stream + events (proven capture pattern).
    static cudaStream_t s_side = nullptr;
    static cudaEvent_t  s_evG[NT_CHUNKS];
    static cudaEvent_t  s_evJoin = nullptr;
    if (!s_side) {
        cudaStreamCreateWithFlags(&s_side, cudaStreamNonBlocking);
        for (int i = 0; i < NT_CHUNKS; i++)
            cudaEventCreateWithFlags(&s_evG[i], cudaEventDisableTiming);
        cudaEventCreateWithFlags(&s_evJoin, cudaEventDisableTiming);
    }

    cudaFuncSetAttribute(gemm_f16pair_kernel,
                         cudaFuncAttributeMaxDynamicSharedMemorySize, SMEM_FORCE_BYTES);

    // Stream 0: GEMM t-chunks. Grid (4, 250): n fastest for X L2 reuse;
    // 1000 CTAs/chunk over 148 SMs -> 7 waves (3.6% quantization waste).
    dim3 ggrid(NDIM / 128, ROWS_CHK / 64);   // (4, 250)
    for (int c = 0; c < NT_CHUNKS; c++) {
        gemm_f16pair_kernel<<<ggrid, 512, SMEM_FORCE_BYTES>>>(x, W1, c * ROWS_CHK);
        cudaEventRecord(s_evG[c], 0);
    }

    // Side stream: scan+reduce for t-chunk c as soon as its GEMM is done —
    // overlaps GEMM chunk c+1. Scan chunks chain on g_u/g_v in-stream.
    for (int c = 0; c < NT_CHUNKS; c++) {
        cudaStreamWaitEvent(s_side, s_evG[c], 0);
        scan_kernel<<<(int)(PLANE / 128), 128, 0, s_side>>>(
            st, a_, b_, c_, d_, v2_, v1_, v0_, tau_, th_, ts_, out, c * T_CHK);
        readout_reduce_kernel<<<T_CHK * BATCH, 128, 0, s_side>>>(
            out, W2, c * T_CHK * BATCH);
    }

    // Join, then li.
    cudaEventRecord(s_evJoin, s_side);
    cudaStreamWaitEvent(0, s_evJoin, 0);
    li_kernel<<<BATCH, 32>>>(stLI, lk_, out);
}

// round 17
// speedup vs baseline: 1.2893x; 1.2893x over previous
#include <cuda_runtime.h>
#include <cuda_fp16.h>
#include <cstdint>
#include <cstddef>
#include <cmath>

// Problem constants
#define T_STEPS 1000
#define BATCH   64
#define NDIM    512
#define KDIM    512
#define MROWS   (BATCH * T_STEPS)   // 64000

// T partition: 6 chunks of 148 + 1 of 112. Each GEMM chunk = 2t CTAs:
// 148 -> 296 = exactly 2 waves on 148 SMs; 112 -> 224 -> 2 waves.
// Total 14 waves vs 16 for the 4x250 split.
#define NCH 7

static constexpr size_t PLANE      = (size_t)BATCH * NDIM;          // 32768
static constexpr size_t STATES_OFF = (size_t)T_STEPS * PLANE;       // outputs plane elems
static constexpr size_t DEC_OFF    = STATES_OFF + 3 * STATES_OFF;   // after states [T,3,B,N]

// Scratch. g_I is [t, b, n]-major: row m = t*BATCH + b.
__device__ __align__(16) float g_I[(size_t)MROWS * NDIM];
__device__ float g_r[T_STEPS * BATCH];
__device__ float g_u[PLANE];     // carried scan state between t-chunks
__device__ float g_v[PLANE];

// ---------------------------------------------------------------------------
// fp16 Dekker-pair: x -> half2(hi=rn16(x), lo=rn16(x-hi)), interleaved along
// mma-k. pass1 (A x B) = hi*hi + lo*lo; pass2 (swap16(A) x B) = hi*lo + lo*hi.
// Sum = full (hi+lo)(hi+lo) product, ~2^-22 relative error.
// ---------------------------------------------------------------------------
__device__ __forceinline__ uint32_t pack_hilo(float x) {
    __half h = __float2half_rn(x);
    float r = x - __half2float(h);
    __half2 p = __halves2half2(h, __float2half_rn(r));
    return *reinterpret_cast<uint32_t*>(&p);
}

__device__ __forceinline__ void mma_f16(float* c, const uint32_t* a, const uint32_t* b) {
    asm volatile(
        "mma.sync.aligned.m16n8k16.row.col.f32.f16.f16.f32 "
        "{%0,%1,%2,%3}, {%4,%5,%6,%7}, {%8,%9}, {%0,%1,%2,%3};\n"
        : "+f"(c[0]), "+f"(c[1]), "+f"(c[2]), "+f"(c[3])
        : "r"(a[0]), "r"(a[1]), "r"(a[2]), "r"(a[3]), "r"(b[0]), "r"(b[1]));
}

__device__ __forceinline__ void ldsm_x4(uint32_t* r, uint32_t saddr) {
    asm volatile("ldmatrix.sync.aligned.m8n8.x4.shared.b16 {%0,%1,%2,%3}, [%4];"
                 : "=r"(r[0]), "=r"(r[1]), "=r"(r[2]), "=r"(r[3]) : "r"(saddr));
}

// ---------------------------------------------------------------------------
// Kernel 1: I[m,:] = X[perm(m),:] @ W1^T — R14-exact core (best measured).
// 512 threads, 16 warps 4x4, warp tile 32x32, ldmatrix loads,
// register-staged double buffer, stride-36-word smem, 72KB.
// ---------------------------------------------------------------------------
#define BKR    32
#define GCHUNK (KDIM / BKR)        // 16
#define WSTR   36
#define TILEW  (128 * WSTR)
#define STAGEW (2 * TILEW)

struct LdgRegs { float4 a[2]; float4 b[2]; };

__device__ __forceinline__ void ldg_chunk(LdgRegs& r, const float* __restrict__ xptr,
                                          const float* __restrict__ wptr, int ck)
{
    const float4* xa = (const float4*)(xptr + ck * BKR);
    const float4* wa = (const float4*)(wptr + ck * BKR);
    r.a[0] = xa[0]; r.a[1] = xa[1];
    r.b[0] = wa[0]; r.b[1] = wa[1];
}

__device__ __forceinline__ void sts_chunk(uint32_t* stage, const LdgRegs& r, int row, int kb)
{
    uint32_t* sA = stage + row * WSTR + kb;
    uint32_t* sB = sA + TILEW;
    const float* fa = (const float*)r.a;
    const float* fb = (const float*)r.b;
    #pragma unroll
    for (int j = 0; j < 2; j++) {
        uint4 w;
        w.x = pack_hilo(fa[j * 4 + 0]); w.y = pack_hilo(fa[j * 4 + 1]);
        w.z = pack_hilo(fa[j * 4 + 2]); w.w = pack_hilo(fa[j * 4 + 3]);
        ((uint4*)sA)[j] = w;
    }
    #pragma unroll
    for (int j = 0; j < 2; j++) {
        uint4 w;
        w.x = pack_hilo(fb[j * 4 + 0]); w.y = pack_hilo(fb[j * 4 + 1]);
        w.z = pack_hilo(fb[j * 4 + 2]); w.w = pack_hilo(fb[j * 4 + 3]);
        ((uint4*)sB)[j] = w;
    }
}

__device__ __forceinline__ void compute_chunk(uint32_t stage_saddr,
                                              float (&acc)[2][4][4],
                                              uint32_t aOff, uint32_t bOff)
{
    #pragma unroll
    for (int s = 0; s < 4; s++) {
        const uint32_t kByte = (uint32_t)(s * 8) * 4u;
        uint32_t A[2][4];
        ldsm_x4(A[0], stage_saddr + aOff + kByte);
        ldsm_x4(A[1], stage_saddr + aOff + (uint32_t)(16 * WSTR * 4) + kByte);
        uint32_t Bt[2][4];
        ldsm_x4(Bt[0], stage_saddr + bOff + kByte);
        ldsm_x4(Bt[1], stage_saddr + bOff + (uint32_t)(16 * WSTR * 4) + kByte);

        #pragma unroll
        for (int mt = 0; mt < 2; mt++)
            #pragma unroll
            for (int nt = 0; nt < 4; nt++)
                mma_f16(acc[mt][nt], A[mt], &Bt[nt >> 1][(nt & 1) * 2]);
        uint32_t As[2][4];
        #pragma unroll
        for (int mt = 0; mt < 2; mt++)
            #pragma unroll
            for (int j = 0; j < 4; j++)
                As[mt][j] = __byte_perm(A[mt][j], 0, 0x1032);
        #pragma unroll
        for (int mt = 0; mt < 2; mt++)
            #pragma unroll
            for (int nt = 0; nt < 4; nt++)
                mma_f16(acc[mt][nt], As[mt], &Bt[nt >> 1][(nt & 1) * 2]);
    }
}

__global__ __launch_bounds__(512, 1) void gemm_f16pair_kernel(const float* __restrict__ X,
                                                              const float* __restrict__ W,
                                                              int bm_base)
{
    extern __shared__ uint32_t smemw[];      // 72KB
    const int tid  = threadIdx.x;
    const int wid  = tid >> 5;
    const int lane = tid & 31;
    const int wm   = wid & 3;
    const int wn   = wid >> 2;
    const int bm   = bm_base + blockIdx.x * 128;
    const int bn   = blockIdx.y * 128;

    const uint32_t smem_saddr = (uint32_t)__cvta_generic_to_shared(smemw);

    const int lm = lane & 7;
    const int aRow = wm * 32 + lm + ((lane >> 3) & 1) * 8;
    const int aWrd = ((lane >> 4) & 1) * 4;
    const uint32_t aOff = (uint32_t)(aRow * WSTR + aWrd) * 4u;
    const int bRow = wn * 32 + lm + ((lane >> 4) & 1) * 8;
    const int bWrd = ((lane >> 3) & 1) * 4;
    const uint32_t bOff = (uint32_t)(TILEW + bRow * WSTR + bWrd) * 4u;

    // loader: m-row = bm + (tid>>2); X row = b*T_STEPS + t for m = t*BATCH + b
    const int lrow = tid >> 2;
    const int lkb  = (tid & 3) * 8;
    const int mrow = bm + lrow;
    const int xrow = (mrow & (BATCH - 1)) * T_STEPS + (mrow / BATCH);
    const float* xptr = X + (size_t)xrow * KDIM + lkb;
    const float* wptr = W + (size_t)(bn + lrow) * KDIM + lkb;

    float acc[2][4][4];
    #pragma unroll
    for (int mt = 0; mt < 2; mt++)
        #pragma unroll
        for (int nt = 0; nt < 4; nt++)
            #pragma unroll
            for (int j = 0; j < 4; j++) acc[mt][nt][j] = 0.f;

    {
        LdgRegs r0;
        ldg_chunk(r0, xptr, wptr, 0);
        sts_chunk(smemw, r0, lrow, lkb);
    }
    __syncthreads();

    #pragma unroll 1
    for (int ck = 0; ck < GCHUNK; ck++) {
        const int cur = ck & 1;
        LdgRegs nr;
        if (ck < GCHUNK - 1) ldg_chunk(nr, xptr, wptr, ck + 1);
        compute_chunk(smem_saddr + (uint32_t)(cur * STAGEW) * 4u, acc, aOff, bOff);
        if (ck < GCHUNK - 1) sts_chunk(smemw + (cur ^ 1) * STAGEW, nr, lrow, lkb);
        __syncthreads();
    }

    #pragma unroll
    for (int mt = 0; mt < 2; mt++) {
        const int r0 = bm + wm * 32 + mt * 16 + (lane >> 2);
        #pragma unroll
        for (int nt = 0; nt < 4; nt++) {
            const int c = bn + wn * 32 + nt * 8 + 2 * (lane & 3);
            *(float2*)(g_I + (size_t)r0 * NDIM + c)       = make_float2(acc[mt][nt][0], acc[mt][nt][1]);
            *(float2*)(g_I + (size_t)(r0 + 8) * NDIM + c) = make_float2(acc[mt][nt][2], acc[mt][nt][3]);
        }
    }
}

// ---------------------------------------------------------------------------
// Kernel 2: Izhikevich scan over t-chunk [tbase, tbase+tlen), runtime tlen.
// I is [t,b,n]: thread g reads g_I[t*PLANE + g] — fully coalesced per warp.
// (u,v) carried via g_u/g_v between chunks (chunk 0 reads state_snn).
// ---------------------------------------------------------------------------
struct NeuronP { float TS, V2, V1, V0, KA, Bp, TH, Cc, D; };

__device__ __forceinline__ void snn_step(float Ic, int t, int g,
                                         const NeuronP& P, float& u, float& v,
                                         float* __restrict__ out)
{
    float t0 = P.V0 - u + Ic;
    t0 = fmaf(P.V1, v, t0);
    t0 = fmaf(P.V2, v * v, t0);
    const float vn = fmaf(P.TS, t0, v);
    const float un = fmaf(P.KA, fmaf(P.Bp, v, -u), u);
    const bool  sp = (vn - P.TH) > 0.f;
    const float s  = sp ? 1.f : 0.f;
    const float vo = sp ? P.Cc : vn;
    const float uo = sp ? (un + P.D) : un;

    out[(size_t)t * PLANE + g] = s;
    const size_t sb = STATES_OFF + (size_t)t * (3 * PLANE) + g;
    out[sb]             = uo;
    out[sb + PLANE]     = vo;
    out[sb + 2 * PLANE] = s;
    u = uo; v = vo;
}

__global__ __launch_bounds__(128) void scan_kernel(
    const float* __restrict__ st,
    const float* __restrict__ pa,  const float* __restrict__ pb,
    const float* __restrict__ pc,  const float* __restrict__ pd,
    const float* __restrict__ pv2, const float* __restrict__ pv1,
    const float* __restrict__ pv0, const float* __restrict__ ptau,
    const float* __restrict__ pth, const float* __restrict__ pts,
    float* __restrict__ out, int tbase, int tlen)
{
    const int g = blockIdx.x * 128 + threadIdx.x;
    const int n = g & (NDIM - 1);

    NeuronP P;
    P.TS = pts[n];
    P.V2 = pv2[n]; P.V1 = pv1[n]; P.V0 = pv0[n];
    P.KA = P.TS / ptau[n] * pa[n];
    P.Bp = pb[n]; P.TH = pth[n]; P.Cc = pc[n]; P.D = pd[n];

    float u, v;
    if (tbase == 0) { u = st[g]; v = st[PLANE + g]; }
    else            { u = g_u[g]; v = g_v[g]; }

    const float* Ip = g_I + (size_t)tbase * PLANE + g;   // step stride = PLANE

    float bufA[8], bufB[8];
    #pragma unroll
    for (int p = 0; p < 8; p++) bufA[p] = __ldcs(Ip + (size_t)p * PLANE);

    // Invariant at loop head: bufA holds steps t0..t0+7, Ip at base+t0*PLANE.
    int t0 = 0;
    #pragma unroll 1
    for (; t0 + 24 <= tlen; t0 += 16) {
        #pragma unroll
        for (int p = 0; p < 8; p++) bufB[p] = __ldcs(Ip + (size_t)(8 + p) * PLANE);
        #pragma unroll
        for (int p = 0; p < 8; p++) snn_step(bufA[p], tbase + t0 + p, g, P, u, v, out);
        #pragma unroll
        for (int p = 0; p < 8; p++) bufA[p] = __ldcs(Ip + (size_t)(16 + p) * PLANE);
        #pragma unroll
        for (int p = 0; p < 8; p++) snn_step(bufB[p], tbase + t0 + 8 + p, g, P, u, v, out);
        Ip += 16 * PLANE;
    }
    // Tail: 8 from bufA, then direct loads for remaining steps.
    #pragma unroll
    for (int p = 0; p < 8; p++) snn_step(bufA[p], tbase + t0 + p, g, P, u, v, out);
    #pragma unroll 1
    for (int p = 8; t0 + p < tlen; p++)
        snn_step(__ldcs(Ip + (size_t)p * PLANE), tbase + t0 + p, g, P, u, v, out);

    g_u[g] = u;
    g_v[g] = v;
}

// ---------------------------------------------------------------------------
// Kernel 3: r[t*B+b] = sum_n s[t,b,n]*W2[n], chunked by t (tb_base offset)
// ---------------------------------------------------------------------------
__global__ __launch_bounds__(128) void readout_reduce_kernel(
    const float* __restrict__ out, const float* __restrict__ W2, int tb_base)
{
    const int tb = tb_base + blockIdx.x;
    const float* sp = out + (size_t)tb * NDIM;
    const int tid = threadIdx.x;

    float sum = 0.f;
    #pragma unroll
    for (int j = 0; j < 4; j++) {
        const int n = tid + j * 128;
        sum = fmaf(sp[n], W2[n], sum);
    }
    #pragma unroll
    for (int o = 16; o > 0; o >>= 1)
        sum += __shfl_xor_sync(0xffffffffu, sum, o);

    __shared__ float ws[4];
    if ((tid & 31) == 0) ws[tid >> 5] = sum;
    __syncthreads();
    if (tid == 0) g_r[tb] = (ws[0] + ws[1]) + (ws[2] + ws[3]);
}

// ---------------------------------------------------------------------------
// Kernel 4: li recurrence — warp-parallel linear-recurrence scan (frozen)
// ---------------------------------------------------------------------------
__global__ void li_kernel(const float* __restrict__ stLI,
                          const float* __restrict__ leak,
                          float* __restrict__ out)
{
    const int b = blockIdx.x;
    const int lane = threadIdx.x;
    const float lk = leak[0];
    const float l1 = lk, l2 = l1 * l1, l4 = l2 * l2, l8 = l4 * l4, l16 = l8 * l8;
    float lpow = lk;
    {
        float sq[5] = {l1, l2, l4, l8, l16};
        #pragma unroll
        for (int i = 0; i < 5; i++)
            if ((lane >> i) & 1) lpow *= sq[i];
    }

    float carry = stLI[b];
    float x = g_r[lane * BATCH + b];

    #pragma unroll 1
    for (int t0 = 0; t0 < T_STEPS; t0 += 32) {
        const int tn = t0 + 32 + lane;
        const float xn = (tn < T_STEPS) ? g_r[tn * BATCH + b] : 0.f;

        float y = x, up;
        up = __shfl_up_sync(0xffffffffu, y, 1);  if (lane >= 1)  y = fmaf(l1,  up, y);
        up = __shfl_up_sync(0xffffffffu, y, 2);  if (lane >= 2)  y = fmaf(l2,  up, y);
        up = __shfl_up_sync(0xffffffffu, y, 4);  if (lane >= 4)  y = fmaf(l4,  up, y);
        up = __shfl_up_sync(0xffffffffu, y, 8);  if (lane >= 8)  y = fmaf(l8,  up, y);
        up = __shfl_up_sync(0xffffffffu, y, 16); if (lane >= 16) y = fmaf(l16, up, y);

        const float li = fmaf(lpow, carry, y);
        if (t0 + lane < T_STEPS)
            out[DEC_OFF + (size_t)(t0 + lane) * BATCH + b] = li;
        carry = __shfl_sync(0xffffffffu, li, 31);
        x = xn;
    }
}

// ---------------------------------------------------------------------------
extern "C" void kernel_launch(void* const* d_in, const int* in_sizes, int n_in,
                              void* d_out, int out_size)
{
    const float* x    = (const float*)d_in[0];
    const float* st   = (const float*)d_in[1];
    const float* stLI = (const float*)d_in[2];
    const float* W1   = (const float*)d_in[3];
    const float* W2   = (const float*)d_in[4];
    const float* a_   = (const float*)d_in[5];
    const float* b_   = (const float*)d_in[6];
    const float* c_   = (const float*)d_in[7];
    const float* d_   = (const float*)d_in[8];
    const float* v2_  = (const float*)d_in[9];
    const float* v1_  = (const float*)d_in[10];
    const float* v0_  = (const float*)d_in[11];
    const float* tau_ = (const float*)d_in[12];
    const float* th_  = (const float*)d_in[13];
    const float* lk_  = (const float*)d_in[14];
    const float* ts_  = (const float*)d_in[15];
    float* out = (float*)d_out;

    // T-chunk sizes: 6x148 + 112 = 1000. Each GEMM chunk = 2*tlen CTAs:
    // 296 (exactly 2 waves) x6, 224 (2 waves) -> 14 waves total vs 16.
    static const int tlens[NCH] = {148, 148, 148, 148, 148, 148, 112};

    // One-time side stream + events (proven capture pattern).
    static cudaStream_t s_side = nullptr;
    static cudaEvent_t  s_evG[NCH];
    static cudaEvent_t  s_evJoin = nullptr;
    if (!s_side) {
        cudaStreamCreateWithFlags(&s_side, cudaStreamNonBlocking);
        for (int i = 0; i < NCH; i++)
            cudaEventCreateWithFlags(&s_evG[i], cudaEventDisableTiming);
        cudaEventCreateWithFlags(&s_evJoin, cudaEventDisableTiming);
    }

    const int smem_bytes = 2 * STAGEW * (int)sizeof(uint32_t);   // 73728
    cudaFuncSetAttribute(gemm_f16pair_kernel,
                         cudaFuncAttributeMaxDynamicSharedMemorySize, smem_bytes);

    // Stream 0: GEMM t-chunks.
    int tb = 0;
    for (int c = 0; c < NCH; c++) {
        const int tlen = tlens[c];
        dim3 ggrid((tlen * BATCH) / 128, NDIM / 128);   // (tlen/2, 4)
        gemm_f16pair_kernel<<<ggrid, 512, smem_bytes>>>(x, W1, tb * BATCH);
        cudaEventRecord(s_evG[c], 0);
        tb += tlen;
    }

    // Side stream: scan+reduce for chunk c after its GEMM — overlaps chunk c+1.
    tb = 0;
    for (int c = 0; c < NCH; c++) {
        const int tlen = tlens[c];
        cudaStreamWaitEvent(s_side, s_evG[c], 0);
        scan_kernel<<<(int)(PLANE / 128), 128, 0, s_side>>>(
            st, a_, b_, c_, d_, v2_, v1_, v0_, tau_, th_, ts_, out, tb, tlen);
        readout_reduce_kernel<<<tlen * BATCH, 128, 0, s_side>>>(
            out, W2, tb * BATCH);
        tb += tlen;
    }

    // Join, then li.
    cudaEventRecord(s_evJoin, s_side);
    cudaStreamWaitEvent(0, s_evJoin, 0);
    li_kernel<<<BATCH, 32>>>(stLI, lk_, out);
}